// round 13
// baseline (speedup 1.0000x reference)
#include <cuda_runtime.h>
#include <cstdint>

#define ND 729
#define NA 180
#define NB 2
#define NH 512
#define NW 512
#define PI_D 3.141592653589793

// Scratch (no cudaMalloc allowed). All zero-initialized at module load.
__device__ float2 g_cs[NA];            // (cos*S, sin*S), S = 729/(2*pi)
__device__ float4 g_edge[NA];          // {f0_b0, f728_b0, f0_b1, f728_b1} (pre-scaled)
__device__ float2 g_corr[NH * NW];     // strip corrections (b0, b1); self-cleaned by k_base

// ---------------------------------------------------------------------------
// Kernel 1 (fused filter + strip). One block per (b, a) row.
// Filter: closed-form piecewise-linear conv kernel
//   h(d) = (1/729)*(1/8 + min(d,729-d)/1458), output pre-scaled by pi/180,
// via prefix sums P,Q of the single row (doubled prefixes reconstructed).
// Filtered row stays in SMEM only. Then the strip pass for THIS row scatters
//   corr = f[idx] - f[728]  over the band 0 < t < 728 (minor width <= 11)
// into g_corr with atomics. Trig computed locally (bit-identical to g_cs).
// ---------------------------------------------------------------------------
__global__ void __launch_bounds__(256) k_fs(const float* __restrict__ sino) {
    __shared__ float  s_sh[768];
    __shared__ float  f_sh[736];
    __shared__ float2 pq[730];
    __shared__ float2 wsum[8];
    __shared__ float2 cs_sh;

    int tid = threadIdx.x, lane = tid & 31, wid = tid >> 5;
    int row = blockIdx.x;
    int b = (row >= NA) ? 1 : 0;
    int a = row - b * NA;
    const float* src = sino + row * ND;

    if (tid == 0) {
        double ang = (double)a * (PI_D / 179.0);
        double S = 729.0 / (2.0 * PI_D);
        float2 c = make_float2((float)(cos(ang) * S), (float)(sin(ang) * S));
        cs_sh = c;
        if (b == 0) g_cs[a] = c;        // k_base reads after this kernel ends
    }

    for (int i = tid; i < 768; i += 256) s_sh[i] = (i < ND) ? __ldg(src + i) : 0.f;
    __syncthreads();

    // --- prefix scan (P, Q) over the row -----------------------------------
    int j0 = tid * 3;
    float2 loc[3];
    float p = 0.f, q = 0.f;
    #pragma unroll
    for (int k = 0; k < 3; k++) {
        int j = j0 + k;
        float v = (j < 768) ? s_sh[j] : 0.f;
        p += v;
        q = fmaf((float)j, v, q);
        loc[k] = make_float2(p, q);
    }
    float tp = p, tq = q;

    #pragma unroll
    for (int o = 1; o < 32; o <<= 1) {
        float ax = __shfl_up_sync(0xffffffffu, p, o);
        float aq = __shfl_up_sync(0xffffffffu, q, o);
        if (lane >= o) { p += ax; q += aq; }
    }
    if (lane == 31) wsum[wid] = make_float2(p, q);
    __syncthreads();

    float wx = 0.f, wq = 0.f;
    #pragma unroll
    for (int w = 0; w < 8; w++)
        if (w < wid) { wx += wsum[w].x; wq += wsum[w].y; }
    float ex = wx + p - tp, eq = wq + q - tq;

    if (tid == 0) pq[0] = make_float2(0.f, 0.f);
    #pragma unroll
    for (int k = 0; k < 3; k++) {
        int j = j0 + k;
        if (j < ND) pq[j + 1] = make_float2(ex + loc[k].x, eq + loc[k].y);
    }
    __syncthreads();

    // --- filtered row -> f_sh ----------------------------------------------
    float T = pq[ND].x, Q9 = pq[ND].y;
    const float sc  = (float)(PI_D / (double)NA);
    const float c0T = T * sc * (1.0f / 5832.0f);
    const float c1  = sc * (1.0f / 1062882.0f);

    for (int n = tid; n < ND; n += 256) {
        float2 A = pq[n + 1];
        float2 B;
        if (n + 365 <= ND) B = pq[n + 365];
        else { float2 r = pq[n + 365 - ND]; B = make_float2(T + r.x, Q9 + r.y + 729.f * r.x); }
        float2 C;
        { float2 r = pq[n + 1]; C = make_float2(T + r.x, Q9 + r.y + 729.f * r.x); }
        float W = (float)(n + 729) * (C.x - B.x) - (C.y - B.y)
                + (B.y - A.y) - (float)n * (B.x - A.x);
        float f = fmaf(c1, W, c0T);
        f_sh[n] = f;
        if (n == 0)   ((float*)(g_edge + a))[2 * b + 0] = f;
        if (n == 728) ((float*)(g_edge + a))[2 * b + 1] = f;
    }
    __syncthreads();

    // --- strip scatter for this row ----------------------------------------
    float cx = cs_sh.x, cy = cs_sh.y;
    float f728 = f_sh[728];
    bool ymin = fabsf(cy) >= fabsf(cx);    // minor axis = y if true
    float A2 = ymin ? cx : cy;             // major coeff
    float Bc = ymin ? cy : cx;             // minor coeff, |Bc| >= 82
    int CNT = (int)(728.f / fabsf(Bc)) + 3;
    float* corrf = (float*)g_corr;

    for (int m = tid; m < NW; m += 256) {
        float mc = (float)m - 256.f;
        float tA = mc * A2;
        float r0 = (0.f - tA) / Bc;
        float r1 = (728.f - tA) / Bc;
        int mn0 = (int)floorf(fminf(r0, r1)) + 256 - 1;
        for (int k = 0; k < CNT; k++) {
            int mn = mn0 + k;
            if ((unsigned)mn < (unsigned)NW) {
                float mnc = (float)mn - 256.f;
                float xcv = ymin ? mc : mnc;
                float ycv = ymin ? mnc : mc;
                float t = fmaf(ycv, cy, xcv * cx);   // identical expr to k_base
                if (t > 0.f && t < 728.f) {
                    float v = f_sh[(int)t];
                    int x = ymin ? m : mn;
                    int y = ymin ? mn : m;
                    atomicAdd(corrf + 2 * (y * NW + x) + b, v - f728);
                }
            }
        }
    }
}

// ---------------------------------------------------------------------------
// Kernel 2 (last): base sums + corr + ReLU -> out; zeroes g_corr for the
// next graph replay (self-cleaning).
// base = sum_a (t(a)>0 ? f[a,728] : f[a,0]) via exact single-flip binary
// search (8 steps, same fma predicate as strip) + 4-channel prefix lookups.
// ---------------------------------------------------------------------------
__global__ void __launch_bounds__(256) k_base(float* __restrict__ out) {
    __shared__ float2 cs[NA];
    __shared__ float4 pre[NA + 1];
    int tid = threadIdx.x;
    for (int i = tid; i < NA; i += 256) cs[i] = g_cs[i];
    if (tid < 32) {
        float4 acc = make_float4(0.f, 0.f, 0.f, 0.f);
        float4 loc[6];
        #pragma unroll
        for (int k = 0; k < 6; k++) {
            int a2 = tid * 6 + k;
            float4 v = (a2 < NA) ? __ldg(g_edge + a2) : make_float4(0.f, 0.f, 0.f, 0.f);
            acc.x += v.x; acc.y += v.y; acc.z += v.z; acc.w += v.w;
            loc[k] = acc;
        }
        float4 tot = acc;
        #pragma unroll
        for (int o = 1; o < 32; o <<= 1) {
            float ax = __shfl_up_sync(0xffffffffu, acc.x, o);
            float ay = __shfl_up_sync(0xffffffffu, acc.y, o);
            float az = __shfl_up_sync(0xffffffffu, acc.z, o);
            float aw = __shfl_up_sync(0xffffffffu, acc.w, o);
            if (tid >= o) { acc.x += ax; acc.y += ay; acc.z += az; acc.w += aw; }
        }
        float4 excl = make_float4(acc.x - tot.x, acc.y - tot.y, acc.z - tot.z, acc.w - tot.w);
        #pragma unroll
        for (int k = 0; k < 6; k++) {
            int a2 = tid * 6 + k;
            if (a2 < NA)
                pre[a2 + 1] = make_float4(excl.x + loc[k].x, excl.y + loc[k].y,
                                          excl.z + loc[k].z, excl.w + loc[k].w);
        }
        if (tid == 0) pre[0] = make_float4(0.f, 0.f, 0.f, 0.f);
    }
    __syncthreads();

    int gid = blockIdx.x * 256 + tid;     // 0..262143
    int x = gid & (NW - 1);
    int y = gid >> 9;
    float xc = (float)x - 256.0f;
    float yc = (float)y - 256.0f;

    bool s0 = fmaf(yc, cs[0].y, xc * cs[0].x) > 0.f;
    int lo = 0, hi = NA;                  // hi: first flipped index (sentinel NA)
    #pragma unroll
    for (int it = 0; it < 8; it++) {
        int mid = (lo + hi) >> 1;
        bool sm = (mid < NA) ? (fmaf(yc, cs[mid].y, xc * cs[mid].x) > 0.f) : !s0;
        if (sm == s0) lo = mid; else hi = mid;
    }
    float4 Pj = pre[hi], Pe = pre[NA];
    float b0, b1;
    if (s0) { b0 = Pj.y + (Pe.x - Pj.x); b1 = Pj.w + (Pe.z - Pj.z); }
    else    { b0 = Pj.x + (Pe.y - Pj.y); b1 = Pj.z + (Pe.w - Pj.w); }

    int p = y * NW + x;
    float2 cr = g_corr[p];
    g_corr[p] = make_float2(0.f, 0.f);    // self-clean for next replay
    out[p] = fmaxf(b0 + cr.x, 0.f);
    out[NH * NW + p] = fmaxf(b1 + cr.y, 0.f);
}

// ---------------------------------------------------------------------------
extern "C" void kernel_launch(void* const* d_in, const int* in_sizes, int n_in,
                              void* d_out, int out_size) {
    const float* sino = (const float*)d_in[0];
    float* out = (float*)d_out;

    k_fs<<<NB * NA, 256>>>(sino);
    k_base<<<(NH * NW) / 256, 256>>>(out);
}

// round 14
// speedup vs baseline: 1.0013x; 1.0013x over previous
#include <cuda_runtime.h>
#include <cstdint>

#define ND 729
#define NA 180
#define NB 2
#define NH 512
#define NW 512
#define PI_D 3.141592653589793

// Scratch (no cudaMalloc allowed). Zero-initialized at module load.
__device__ float2 g_cs[NA];            // (cos*S, sin*S), S = 729/(2*pi)
__device__ float4 g_edge[NA];          // {f0_b0, f728_b0, f0_b1, f728_b1} (pre-scaled)
__device__ float4 g_pre[NA + 1];       // exclusive 4-channel prefix of g_edge
__device__ float2 g_corr[NH * NW];     // strip corrections; self-cleaned by k_base
__device__ unsigned g_ticket;          // block-completion ticket; self-cleaned

// ---------------------------------------------------------------------------
// Kernel 1 (fused filter + strip + last-block prefix). One block per (b,a) row.
// Filter: h(d) = (1/729)*(1/8 + min(d,729-d)/1458), pre-scaled by pi/180,
// via prefix sums P,Q of the row. Filtered row lives only in SMEM. The strip
// pass scatters corr = f[idx]-f[728] over the band 0 < t < 728 into g_corr.
// Last block (ticket) computes g_pre from g_edge and resets the ticket.
// ---------------------------------------------------------------------------
__global__ void __launch_bounds__(256) k_fs(const float* __restrict__ sino) {
    __shared__ float  s_sh[768];
    __shared__ float  f_sh[736];
    __shared__ float2 pq[730];
    __shared__ float2 wsum[8];
    __shared__ float2 cs_sh;
    __shared__ bool   is_last;

    int tid = threadIdx.x, lane = tid & 31, wid = tid >> 5;
    int row = blockIdx.x;
    int b = (row >= NA) ? 1 : 0;
    int a = row - b * NA;
    const float* src = sino + row * ND;

    if (tid == 0) {
        double ang = (double)a * (PI_D / 179.0);
        double S = 729.0 / (2.0 * PI_D);
        float2 c = make_float2((float)(cos(ang) * S), (float)(sin(ang) * S));
        cs_sh = c;
        if (b == 0) g_cs[a] = c;
    }

    for (int i = tid; i < 768; i += 256) s_sh[i] = (i < ND) ? __ldg(src + i) : 0.f;
    __syncthreads();

    // --- prefix scan (P, Q) over the row -----------------------------------
    int j0 = tid * 3;
    float2 loc[3];
    float p = 0.f, q = 0.f;
    #pragma unroll
    for (int k = 0; k < 3; k++) {
        int j = j0 + k;
        float v = (j < 768) ? s_sh[j] : 0.f;
        p += v;
        q = fmaf((float)j, v, q);
        loc[k] = make_float2(p, q);
    }
    float tp = p, tq = q;

    #pragma unroll
    for (int o = 1; o < 32; o <<= 1) {
        float ax = __shfl_up_sync(0xffffffffu, p, o);
        float aq = __shfl_up_sync(0xffffffffu, q, o);
        if (lane >= o) { p += ax; q += aq; }
    }
    if (lane == 31) wsum[wid] = make_float2(p, q);
    __syncthreads();

    float wx = 0.f, wq = 0.f;
    #pragma unroll
    for (int w = 0; w < 8; w++)
        if (w < wid) { wx += wsum[w].x; wq += wsum[w].y; }
    float ex = wx + p - tp, eq = wq + q - tq;

    if (tid == 0) pq[0] = make_float2(0.f, 0.f);
    #pragma unroll
    for (int k = 0; k < 3; k++) {
        int j = j0 + k;
        if (j < ND) pq[j + 1] = make_float2(ex + loc[k].x, eq + loc[k].y);
    }
    __syncthreads();

    // --- filtered row -> f_sh ----------------------------------------------
    float T = pq[ND].x, Q9 = pq[ND].y;
    const float sc  = (float)(PI_D / (double)NA);
    const float c0T = T * sc * (1.0f / 5832.0f);
    const float c1  = sc * (1.0f / 1062882.0f);

    for (int n = tid; n < ND; n += 256) {
        float2 A = pq[n + 1];
        float2 B;
        if (n + 365 <= ND) B = pq[n + 365];
        else { float2 r = pq[n + 365 - ND]; B = make_float2(T + r.x, Q9 + r.y + 729.f * r.x); }
        float2 C;
        { float2 r = pq[n + 1]; C = make_float2(T + r.x, Q9 + r.y + 729.f * r.x); }
        float W = (float)(n + 729) * (C.x - B.x) - (C.y - B.y)
                + (B.y - A.y) - (float)n * (B.x - A.x);
        float f = fmaf(c1, W, c0T);
        f_sh[n] = f;
        if (n == 0)   ((float*)(g_edge + a))[2 * b + 0] = f;
        if (n == 728) ((float*)(g_edge + a))[2 * b + 1] = f;
    }
    __threadfence();   // publish this block's g_edge writes (writer-side fence)
    __syncthreads();

    // --- strip scatter for this row ----------------------------------------
    float cx = cs_sh.x, cy = cs_sh.y;
    float f728 = f_sh[728];
    bool ymin = fabsf(cy) >= fabsf(cx);    // minor axis = y if true
    float A2 = ymin ? cx : cy;             // major coeff
    float Bc = ymin ? cy : cx;             // minor coeff, |Bc| >= 82
    int CNT = (int)(728.f / fabsf(Bc)) + 3;
    float* corrf = (float*)g_corr;

    for (int m = tid; m < NW; m += 256) {
        float mc = (float)m - 256.f;
        float tA = mc * A2;
        float r0 = (0.f - tA) / Bc;
        float r1 = (728.f - tA) / Bc;
        int mn0 = (int)floorf(fminf(r0, r1)) + 256 - 1;
        for (int k = 0; k < CNT; k++) {
            int mn = mn0 + k;
            if ((unsigned)mn < (unsigned)NW) {
                float mnc = (float)mn - 256.f;
                float xcv = ymin ? mc : mnc;
                float ycv = ymin ? mnc : mc;
                float t = fmaf(ycv, cy, xcv * cx);   // identical expr to k_base
                if (t > 0.f && t < 728.f) {
                    float v = f_sh[(int)t];
                    int x = ymin ? m : mn;
                    int y = ymin ? mn : m;
                    atomicAdd(corrf + 2 * (y * NW + x) + b, v - f728);
                }
            }
        }
    }

    // --- ticket: last block builds g_pre, resets ticket --------------------
    if (tid == 0) {
        unsigned t = atomicAdd(&g_ticket, 1u);
        is_last = (t == (unsigned)(NB * NA - 1));
    }
    __syncthreads();
    if (is_last) {
        __threadfence();   // acquire all blocks' g_edge writes
        if (tid < 32) {
            float4 acc = make_float4(0.f, 0.f, 0.f, 0.f);
            float4 lc[6];
            #pragma unroll
            for (int k = 0; k < 6; k++) {
                int a2 = tid * 6 + k;
                float4 v = (a2 < NA) ? g_edge[a2] : make_float4(0.f, 0.f, 0.f, 0.f);
                acc.x += v.x; acc.y += v.y; acc.z += v.z; acc.w += v.w;
                lc[k] = acc;
            }
            float4 tot = acc;
            #pragma unroll
            for (int o = 1; o < 32; o <<= 1) {
                float ax = __shfl_up_sync(0xffffffffu, acc.x, o);
                float ay = __shfl_up_sync(0xffffffffu, acc.y, o);
                float az = __shfl_up_sync(0xffffffffu, acc.z, o);
                float aw = __shfl_up_sync(0xffffffffu, acc.w, o);
                if (tid >= o) { acc.x += ax; acc.y += ay; acc.z += az; acc.w += aw; }
            }
            float4 excl = make_float4(acc.x - tot.x, acc.y - tot.y,
                                      acc.z - tot.z, acc.w - tot.w);
            #pragma unroll
            for (int k = 0; k < 6; k++) {
                int a2 = tid * 6 + k;
                if (a2 < NA)
                    g_pre[a2 + 1] = make_float4(excl.x + lc[k].x, excl.y + lc[k].y,
                                                excl.z + lc[k].z, excl.w + lc[k].w);
            }
            if (tid == 0) {
                g_pre[0] = make_float4(0.f, 0.f, 0.f, 0.f);
                __threadfence();
                g_ticket = 0;          // self-clean for next graph replay
            }
        }
    }
}

// ---------------------------------------------------------------------------
// Kernel 2: base sums + corr + ReLU -> out; zeroes g_corr (self-cleaning).
// base = sum_a (t(a)>0 ? f[a,728] : f[a,0]) via exact single-flip binary
// search (8 steps, same fma predicate as strip) + g_pre lookups.
// Shared staging is fully cooperative: 2 coalesced loads per thread, no
// serial warp-0 scan.
// ---------------------------------------------------------------------------
__global__ void __launch_bounds__(256) k_base(float* __restrict__ out) {
    __shared__ float2 cs[NA];
    __shared__ float4 pre[NA + 1];
    int tid = threadIdx.x;
    if (tid < NA) cs[tid] = __ldg(&g_cs[tid]);
    for (int i = tid; i < NA + 1; i += 256) pre[i] = __ldg(&g_pre[i]);
    __syncthreads();

    int gid = blockIdx.x * 256 + tid;     // 0..262143
    int x = gid & (NW - 1);
    int y = gid >> 9;
    float xc = (float)x - 256.0f;
    float yc = (float)y - 256.0f;

    bool s0 = fmaf(yc, cs[0].y, xc * cs[0].x) > 0.f;
    int lo = 0, hi = NA;                  // hi: first flipped index (sentinel NA)
    #pragma unroll
    for (int it = 0; it < 8; it++) {
        int mid = (lo + hi) >> 1;
        bool sm = (mid < NA) ? (fmaf(yc, cs[mid].y, xc * cs[mid].x) > 0.f) : !s0;
        if (sm == s0) lo = mid; else hi = mid;
    }
    float4 Pj = pre[hi], Pe = pre[NA];
    float b0, b1;
    if (s0) { b0 = Pj.y + (Pe.x - Pj.x); b1 = Pj.w + (Pe.z - Pj.z); }
    else    { b0 = Pj.x + (Pe.y - Pj.y); b1 = Pj.z + (Pe.w - Pj.w); }

    int p = y * NW + x;
    float2 cr = g_corr[p];
    g_corr[p] = make_float2(0.f, 0.f);    // self-clean for next replay
    out[p] = fmaxf(b0 + cr.x, 0.f);
    out[NH * NW + p] = fmaxf(b1 + cr.y, 0.f);
}

// ---------------------------------------------------------------------------
extern "C" void kernel_launch(void* const* d_in, const int* in_sizes, int n_in,
                              void* d_out, int out_size) {
    const float* sino = (const float*)d_in[0];
    float* out = (float*)d_out;

    k_fs<<<NB * NA, 256>>>(sino);
    k_base<<<(NH * NW) / 256, 256>>>(out);
}

// round 15
// speedup vs baseline: 1.0904x; 1.0890x over previous
#include <cuda_runtime.h>
#include <cstdint>

#define ND 729
#define NA 180
#define NB 2
#define NH 512
#define NW 512
#define PI_D 3.141592653589793

// Scratch (no cudaMalloc allowed). Zero-initialized at module load.
__device__ float2 g_cs[NA];            // (cos*S, sin*S), S = 729/(2*pi)
__device__ float4 g_edge[NA];          // {f0_b0, f728_b0, f0_b1, f728_b1} (pre-scaled)
__device__ float4 g_pre[NA + 1];       // exclusive 4-channel prefix of g_edge
__device__ float2 g_corr[NH * NW];     // strip corrections; self-cleaned by k_base
__device__ unsigned g_ticket;          // block-completion ticket; self-cleaned

// ---------------------------------------------------------------------------
// Kernel 1 (fused filter + strip + ticketed prefix). One block per (b,a) row.
// Filter: h(d) = (1/729)*(1/8 + min(d,729-d)/1458), pre-scaled by pi/180,
// via prefix sums P,Q of the row. Filtered row lives only in SMEM. Edge
// publication + ticket happen BEFORE the strip phase (tid0-only fence), so
// the 360th block's g_pre scan overlaps the other blocks' strip scatter.
// ---------------------------------------------------------------------------
__global__ void __launch_bounds__(256) k_fs(const float* __restrict__ sino) {
    __shared__ float  s_sh[768];
    __shared__ float  f_sh[736];
    __shared__ float2 pq[730];
    __shared__ float2 wsum[8];
    __shared__ float2 cs_sh;
    __shared__ bool   is_last;

    int tid = threadIdx.x, lane = tid & 31, wid = tid >> 5;
    int row = blockIdx.x;
    int b = (row >= NA) ? 1 : 0;
    int a = row - b * NA;
    const float* src = sino + row * ND;

    if (tid == 0) {
        double ang = (double)a * (PI_D / 179.0);
        double S = 729.0 / (2.0 * PI_D);
        float2 c = make_float2((float)(cos(ang) * S), (float)(sin(ang) * S));
        cs_sh = c;
        if (b == 0) g_cs[a] = c;
    }

    for (int i = tid; i < 768; i += 256) s_sh[i] = (i < ND) ? __ldg(src + i) : 0.f;
    __syncthreads();

    // --- prefix scan (P, Q) over the row -----------------------------------
    int j0 = tid * 3;
    float2 loc[3];
    float p = 0.f, q = 0.f;
    #pragma unroll
    for (int k = 0; k < 3; k++) {
        int j = j0 + k;
        float v = (j < 768) ? s_sh[j] : 0.f;
        p += v;
        q = fmaf((float)j, v, q);
        loc[k] = make_float2(p, q);
    }
    float tp = p, tq = q;

    #pragma unroll
    for (int o = 1; o < 32; o <<= 1) {
        float ax = __shfl_up_sync(0xffffffffu, p, o);
        float aq = __shfl_up_sync(0xffffffffu, q, o);
        if (lane >= o) { p += ax; q += aq; }
    }
    if (lane == 31) wsum[wid] = make_float2(p, q);
    __syncthreads();

    float wx = 0.f, wq = 0.f;
    #pragma unroll
    for (int w = 0; w < 8; w++)
        if (w < wid) { wx += wsum[w].x; wq += wsum[w].y; }
    float ex = wx + p - tp, eq = wq + q - tq;

    if (tid == 0) pq[0] = make_float2(0.f, 0.f);
    #pragma unroll
    for (int k = 0; k < 3; k++) {
        int j = j0 + k;
        if (j < ND) pq[j + 1] = make_float2(ex + loc[k].x, eq + loc[k].y);
    }
    __syncthreads();

    // --- filtered row -> f_sh ----------------------------------------------
    float T = pq[ND].x, Q9 = pq[ND].y;
    const float sc  = (float)(PI_D / (double)NA);
    const float c0T = T * sc * (1.0f / 5832.0f);
    const float c1  = sc * (1.0f / 1062882.0f);

    for (int n = tid; n < ND; n += 256) {
        float2 A = pq[n + 1];
        float2 B;
        if (n + 365 <= ND) B = pq[n + 365];
        else { float2 r = pq[n + 365 - ND]; B = make_float2(T + r.x, Q9 + r.y + 729.f * r.x); }
        float2 C;
        { float2 r = pq[n + 1]; C = make_float2(T + r.x, Q9 + r.y + 729.f * r.x); }
        float W = (float)(n + 729) * (C.x - B.x) - (C.y - B.y)
                + (B.y - A.y) - (float)n * (B.x - A.x);
        f_sh[n] = fmaf(c1, W, c0T);
    }
    __syncthreads();

    // --- tid0: publish edges, fence once, take ticket (BEFORE strip) -------
    if (tid == 0) {
        float* ep = (float*)(g_edge + a);
        ep[2 * b + 0] = f_sh[0];
        ep[2 * b + 1] = f_sh[728];
        __threadfence();                       // release my edge writes
        unsigned t = atomicAdd(&g_ticket, 1u);
        is_last = (t == (unsigned)(NB * NA - 1));
    }

    // --- strip scatter for this row ----------------------------------------
    float cx = cs_sh.x, cy = cs_sh.y;
    float f728 = f_sh[728];
    bool ymin = fabsf(cy) >= fabsf(cx);    // minor axis = y if true
    float A2 = ymin ? cx : cy;             // major coeff
    float Bc = ymin ? cy : cx;             // minor coeff, |Bc| >= 82
    int CNT = (int)(728.f / fabsf(Bc)) + 3;
    float* corrf = (float*)g_corr;

    for (int m = tid; m < NW; m += 256) {
        float mc = (float)m - 256.f;
        float tA = mc * A2;
        float r0 = (0.f - tA) / Bc;
        float r1 = (728.f - tA) / Bc;
        int mn0 = (int)floorf(fminf(r0, r1)) + 256 - 1;
        for (int k = 0; k < CNT; k++) {
            int mn = mn0 + k;
            if ((unsigned)mn < (unsigned)NW) {
                float mnc = (float)mn - 256.f;
                float xcv = ymin ? mc : mnc;
                float ycv = ymin ? mnc : mc;
                float t = fmaf(ycv, cy, xcv * cx);   // identical expr to k_base
                if (t > 0.f && t < 728.f) {
                    float v = f_sh[(int)t];
                    int x = ymin ? m : mn;
                    int y = ymin ? mn : m;
                    atomicAdd(corrf + 2 * (y * NW + x) + b, v - f728);
                }
            }
        }
    }
    __syncthreads();

    // --- last block: 4-channel prefix of g_edge -> g_pre -------------------
    if (is_last) {
        __threadfence();   // acquire all blocks' edge writes
        if (tid < 32) {
            float4 v[6];
            #pragma unroll
            for (int k = 0; k < 6; k++) {   // independent loads
                int a2 = tid * 6 + k;
                v[k] = (a2 < NA) ? g_edge[a2] : make_float4(0.f, 0.f, 0.f, 0.f);
            }
            float4 acc = make_float4(0.f, 0.f, 0.f, 0.f);
            float4 lc[6];
            #pragma unroll
            for (int k = 0; k < 6; k++) {
                acc.x += v[k].x; acc.y += v[k].y; acc.z += v[k].z; acc.w += v[k].w;
                lc[k] = acc;
            }
            float4 tot = acc;
            #pragma unroll
            for (int o = 1; o < 32; o <<= 1) {
                float ax = __shfl_up_sync(0xffffffffu, acc.x, o);
                float ay = __shfl_up_sync(0xffffffffu, acc.y, o);
                float az = __shfl_up_sync(0xffffffffu, acc.z, o);
                float aw = __shfl_up_sync(0xffffffffu, acc.w, o);
                if (tid >= o) { acc.x += ax; acc.y += ay; acc.z += az; acc.w += aw; }
            }
            float4 excl = make_float4(acc.x - tot.x, acc.y - tot.y,
                                      acc.z - tot.z, acc.w - tot.w);
            #pragma unroll
            for (int k = 0; k < 6; k++) {
                int a2 = tid * 6 + k;
                if (a2 < NA)
                    g_pre[a2 + 1] = make_float4(excl.x + lc[k].x, excl.y + lc[k].y,
                                                excl.z + lc[k].z, excl.w + lc[k].w);
            }
            if (tid == 0) {
                g_pre[0] = make_float4(0.f, 0.f, 0.f, 0.f);
                __threadfence();
                g_ticket = 0;          // self-clean for next graph replay
            }
        }
    }
}

// ---------------------------------------------------------------------------
// Kernel 2: base sums + corr + ReLU -> out; zeroes g_corr (self-cleaning).
// base = sum_a (t(a)>0 ? f[a,728] : f[a,0]) via exact single-flip binary
// search (8 steps, same fma predicate as strip) + g_pre lookups.
// ---------------------------------------------------------------------------
__global__ void __launch_bounds__(256) k_base(float* __restrict__ out) {
    __shared__ float2 cs[NA];
    __shared__ float4 pre[NA + 1];
    int tid = threadIdx.x;
    if (tid < NA) cs[tid] = __ldg(&g_cs[tid]);
    for (int i = tid; i < NA + 1; i += 256) pre[i] = __ldg(&g_pre[i]);
    __syncthreads();

    int gid = blockIdx.x * 256 + tid;     // 0..262143
    int x = gid & (NW - 1);
    int y = gid >> 9;
    float xc = (float)x - 256.0f;
    float yc = (float)y - 256.0f;

    bool s0 = fmaf(yc, cs[0].y, xc * cs[0].x) > 0.f;
    int lo = 0, hi = NA;                  // hi: first flipped index (sentinel NA)
    #pragma unroll
    for (int it = 0; it < 8; it++) {
        int mid = (lo + hi) >> 1;
        bool sm = (mid < NA) ? (fmaf(yc, cs[mid].y, xc * cs[mid].x) > 0.f) : !s0;
        if (sm == s0) lo = mid; else hi = mid;
    }
    float4 Pj = pre[hi], Pe = pre[NA];
    float b0, b1;
    if (s0) { b0 = Pj.y + (Pe.x - Pj.x); b1 = Pj.w + (Pe.z - Pj.z); }
    else    { b0 = Pj.x + (Pe.y - Pj.y); b1 = Pj.z + (Pe.w - Pj.w); }

    int p = y * NW + x;
    float2 cr = g_corr[p];
    g_corr[p] = make_float2(0.f, 0.f);    // self-clean for next replay
    out[p] = fmaxf(b0 + cr.x, 0.f);
    out[NH * NW + p] = fmaxf(b1 + cr.y, 0.f);
}

// ---------------------------------------------------------------------------
extern "C" void kernel_launch(void* const* d_in, const int* in_sizes, int n_in,
                              void* d_out, int out_size) {
    const float* sino = (const float*)d_in[0];
    float* out = (float*)d_out;

    k_fs<<<NB * NA, 256>>>(sino);
    k_base<<<(NH * NW) / 256, 256>>>(out);
}